// round 1
// baseline (speedup 1.0000x reference)
#include <cuda_runtime.h>
#include <cstdint>

// ---------------------------------------------------------------------------
// Problem constants (B=2, C=192, H=W=256, WS=8, NH=6, hd=32, DF=768)
// ---------------------------------------------------------------------------
#define BATCH 2
#define CH    192
#define HH    256
#define WW    256
#define NTOK  (BATCH*HH*WW)        // 131072 tokens
#define NHEAD 6
#define HD    32
#define DF    768
#define NWIN  2048                 // Bw
#define WN    64                   // tokens per window

// ---------------------------------------------------------------------------
// Scratch (static device allocations — allowed; no cudaMalloc anywhere)
// ---------------------------------------------------------------------------
__device__ float d_perm[NTOK * CH];      // 96MB  : LN1 output in "window" layout
__device__ float d_qkv [NTOK * 3 * CH];  // 288MB : qkv
__device__ float d_obuf[NTOK * CH];      // 96MB  : attention output
__device__ float d_ybuf[NTOK * CH];      // 96MB  : proj + residual (window layout)
__device__ float d_zt  [NTOK * CH];      // 96MB  : LN2 output, token-major spatial
__device__ float d_gbuf[NTOK * DF];      // 384MB : gated FFN hidden
__device__ float d_f1T [CH * DF];
__device__ float d_f2T [CH * DF];
__device__ float d_f3T [DF * CH];

// ---------------------------------------------------------------------------
// Kernel 1: LN1 over channels + channel-layout window partition (permute)
//   thread = pixel (b,h,w). Write channel c to
//   P = ((((b*24 + c/8)*32 + h/8)*8 + c%8)*8 + h%8)*256 + w
// ---------------------------------------------------------------------------
__global__ void ln1_kernel(const float* __restrict__ x,
                           const float* __restrict__ g,
                           const float* __restrict__ b,
                           float* __restrict__ perm)
{
    int p = blockIdx.x * blockDim.x + threadIdx.x;
    if (p >= NTOK) return;
    int w  = p & 255;
    int h  = (p >> 8) & 255;
    int bb = p >> 16;
    const float* xp = x + (size_t)bb * CH * (HH*WW) + h * WW + w;

    float sum = 0.f, sq = 0.f;
    #pragma unroll 4
    for (int c = 0; c < CH; c++) {
        float v = xp[(size_t)c * (HH*WW)];
        sum += v; sq += v * v;
    }
    float mean = sum * (1.f / CH);
    float var  = sq * (1.f / CH) - mean * mean;
    float inv  = rsqrtf(fmaxf(var, 0.f) + 1e-5f);

    int h1 = h >> 3, h2 = h & 7;
    #pragma unroll 4
    for (int c = 0; c < CH; c++) {
        float v = (xp[(size_t)c * (HH*WW)] - mean) * inv * g[c] + b[c];
        int c1 = c >> 3, c2 = c & 7;
        size_t P = (((((size_t)bb * 24 + c1) * 32 + h1) * 8 + c2) * 8 + h2) * 256 + w;
        perm[P] = v;
    }
}

// ---------------------------------------------------------------------------
// Kernel 2: transpose FFN weights (fc1,fc2: (768,192)->(192,768); fc3: (192,768)->(768,192))
// ---------------------------------------------------------------------------
__global__ void transpose_w(const float* __restrict__ f1, const float* __restrict__ f2,
                            const float* __restrict__ f3,
                            float* __restrict__ t1, float* __restrict__ t2,
                            float* __restrict__ t3)
{
    int i = blockIdx.x * blockDim.x + threadIdx.x;
    if (i >= CH * DF) return;
    int o = i / CH, c = i % CH;        // f1,f2 are (DF, CH)
    t1[c * DF + o] = f1[i];
    t2[c * DF + o] = f2[i];
    int pp = i / DF, q = i % DF;       // f3 is (CH, DF)
    t3[q * CH + pp] = f3[i];
}

// ---------------------------------------------------------------------------
// Tiled SGEMM: C[M,N] = A[M,K] @ B[K,N]  (A,B row-major)
// BM=128, BN=64, BK=16, 256 threads, 8x4 per thread.
// EPI: 0 = +bias -> row-major out (QKV)
//      1 = +bias + resid[m*N+n] -> row-major out (proj + residual)
//      2 = dual-B: sigmoid(acc1+b1)*(acc2+b2) -> row-major out (gated FFN)
//      3 = +bias + resid[m*192+n] -> scatter to (B,C,H,W) (final)
// SWAP: thread map with tx along M (coalesces EPI=3 scatter)
// ---------------------------------------------------------------------------
template<int EPI, bool SWAP>
__global__ __launch_bounds__(256)
void gemm_kernel(const float* __restrict__ A,
                 const float* __restrict__ B,
                 const float* __restrict__ B2,
                 const float* __restrict__ bias1,
                 const float* __restrict__ bias2,
                 const float* __restrict__ resid,
                 float* __restrict__ out,
                 int M, int N, int K)
{
    constexpr int BM = 128, BN = 64, BK = 16, TM = 8, TN = 4;
    __shared__ float As [BK][BM];
    __shared__ float Bs [BK][BN];
    __shared__ float Bs2[BK][BN];

    int tid = threadIdx.x;
    int tx = tid & 15, ty = tid >> 4;
    int row_base = SWAP ? tx * TM : ty * TM;
    int col_base = SWAP ? ty * TN : tx * TN;
    const int M0 = blockIdx.y * BM;
    const int N0 = blockIdx.x * BN;

    float acc [TM][TN] = {};
    float acc2[TM][TN] = {};

    for (int k0 = 0; k0 < K; k0 += BK) {
        { // load A tile (transposed into smem)
            int kk = tid & 15, m = tid >> 4;
            #pragma unroll
            for (int r = 0; r < 8; r++)
                As[kk][m + r * 16] = A[(size_t)(M0 + m + r * 16) * K + k0 + kk];
        }
        { // load B tile(s)
            int n = tid & 63, kk = tid >> 6;
            #pragma unroll
            for (int r = 0; r < 4; r++) {
                Bs[kk + r * 4][n] = B[(size_t)(k0 + kk + r * 4) * N + N0 + n];
                if (EPI == 2)
                    Bs2[kk + r * 4][n] = B2[(size_t)(k0 + kk + r * 4) * N + N0 + n];
            }
        }
        __syncthreads();
        #pragma unroll
        for (int kk = 0; kk < BK; kk++) {
            float4 a0 = *(const float4*)&As[kk][row_base];
            float4 a1 = *(const float4*)&As[kk][row_base + 4];
            float4 bv = *(const float4*)&Bs[kk][col_base];
            float a[8] = {a0.x, a0.y, a0.z, a0.w, a1.x, a1.y, a1.z, a1.w};
            float bb[4] = {bv.x, bv.y, bv.z, bv.w};
            #pragma unroll
            for (int i = 0; i < TM; i++)
                #pragma unroll
                for (int j = 0; j < TN; j++)
                    acc[i][j] += a[i] * bb[j];
            if (EPI == 2) {
                float4 b2v = *(const float4*)&Bs2[kk][col_base];
                float b2a[4] = {b2v.x, b2v.y, b2v.z, b2v.w};
                #pragma unroll
                for (int i = 0; i < TM; i++)
                    #pragma unroll
                    for (int j = 0; j < TN; j++)
                        acc2[i][j] += a[i] * b2a[j];
            }
        }
        __syncthreads();
    }

    #pragma unroll
    for (int i = 0; i < TM; i++) {
        int m = M0 + row_base + i;
        #pragma unroll
        for (int j = 0; j < TN; j++) {
            int n = N0 + col_base + j;
            float v = acc[i][j];
            if (EPI == 0) {
                out[(size_t)m * N + n] = v + bias1[n];
            } else if (EPI == 1) {
                out[(size_t)m * N + n] = v + bias1[n] + resid[(size_t)m * N + n];
            } else if (EPI == 2) {
                float h1 = 1.f / (1.f + __expf(-(v + bias1[n])));
                float h2 = acc2[i][j] + bias2[n];
                out[(size_t)m * N + n] = h1 * h2;
            } else { // EPI == 3: final out, scatter to (B,C,H,W) + residual z
                float val = v + bias1[n] + resid[(size_t)m * CH + n];
                int bb = m >> 16;
                int hw = m & 65535;
                out[(((size_t)bb * CH + n) << 16) + hw] = val;
            }
        }
    }
}

// ---------------------------------------------------------------------------
// Kernel 3: window attention. block = (window, head), 64 threads (row each).
// ---------------------------------------------------------------------------
__global__ __launch_bounds__(64)
void attn_kernel(const float* __restrict__ qkv,
                 const float* __restrict__ bias_table,
                 float* __restrict__ obuf)
{
    int bw   = blockIdx.x;
    int head = blockIdx.y;
    __shared__ float ks[WN][HD];
    __shared__ float vs[WN][HD];
    __shared__ float bs[225];

    int tid = threadIdx.x;
    const float* base = qkv + (size_t)bw * WN * (3 * CH);

    for (int i = tid; i < 225; i += 64)
        bs[i] = bias_table[i * NHEAD + head];
    for (int e = tid; e < WN * HD; e += 64) {
        int n = e >> 5, d = e & 31;
        ks[n][d] = base[(size_t)n * (3 * CH) + CH     + head * HD + d];
        vs[n][d] = base[(size_t)n * (3 * CH) + 2 * CH + head * HD + d];
    }

    const float scale = 0.17677669529663687f; // 32^-0.5
    float q[HD];
    const float* qrow = base + (size_t)tid * (3 * CH) + head * HD;
    #pragma unroll
    for (int d = 0; d < HD; d++) q[d] = qrow[d] * scale;
    __syncthreads();

    int it = tid >> 3, jt = tid & 7;
    float s[WN];
    float mx = -1e30f;
    #pragma unroll 4
    for (int m = 0; m < WN; m++) {
        float a = 0.f;
        #pragma unroll
        for (int d = 0; d < HD; d++) a += q[d] * ks[m][d];
        int im = m >> 3, jm = m & 7;
        a += bs[(it - im + 7) * 15 + (jt - jm + 7)];
        s[m] = a;
        mx = fmaxf(mx, a);
    }
    float sum = 0.f;
    #pragma unroll 4
    for (int m = 0; m < WN; m++) { s[m] = __expf(s[m] - mx); sum += s[m]; }
    float inv = 1.f / sum;

    float o[HD] = {};
    #pragma unroll 4
    for (int m = 0; m < WN; m++) {
        float p = s[m];
        #pragma unroll
        for (int d = 0; d < HD; d++) o[d] += p * vs[m][d];
    }
    float* orow = obuf + ((size_t)bw * WN + tid) * CH + head * HD;
    #pragma unroll
    for (int d = 0; d < HD; d++) orow[d] = o[d] * inv;
}

// ---------------------------------------------------------------------------
// Kernel 4: LN2 over contiguous 192-rows of y (window layout) + window_reverse
// permutation to token-major spatial order. One warp per row.
// row -> (b, d1, d2, d3, d4): h = d1*8+d3, w = d2*8+d4
// ---------------------------------------------------------------------------
__global__ __launch_bounds__(256)
void ln2_kernel(const float* __restrict__ y,
                const float* __restrict__ g,
                const float* __restrict__ b,
                float* __restrict__ zt)
{
    int tid  = threadIdx.x;
    int lane = tid & 31, wid = tid >> 5;
    int row  = blockIdx.x * 8 + wid;
    const float* yr = y + (size_t)row * CH;

    float v[6];
    float sum = 0.f, sq = 0.f;
    #pragma unroll
    for (int k = 0; k < 6; k++) {
        v[k] = yr[lane + k * 32];
        sum += v[k]; sq += v[k] * v[k];
    }
    #pragma unroll
    for (int o = 16; o > 0; o >>= 1) {
        sum += __shfl_xor_sync(0xffffffffu, sum, o);
        sq  += __shfl_xor_sync(0xffffffffu, sq,  o);
    }
    float mean = sum * (1.f / CH);
    float var  = sq * (1.f / CH) - mean * mean;
    float inv  = rsqrtf(fmaxf(var, 0.f) + 1e-5f);

    int d4 = row & 7, d3 = (row >> 3) & 7, d2 = (row >> 6) & 31,
        d1 = (row >> 11) & 31, bb = row >> 16;
    int h = d1 * 8 + d3, w = d2 * 8 + d4;
    int t = ((bb * 256 + h) << 8) + w;
    float* zr = zt + (size_t)t * CH;
    #pragma unroll
    for (int k = 0; k < 6; k++) {
        int c = lane + k * 32;
        zr[c] = (v[k] - mean) * inv * g[c] + b[c];
    }
}

// ---------------------------------------------------------------------------
// kernel_launch
// ---------------------------------------------------------------------------
extern "C" void kernel_launch(void* const* d_in, const int* in_sizes, int n_in,
                              void* d_out, int out_size)
{
    const float* x          = (const float*)d_in[0];
    const float* ln1_g      = (const float*)d_in[1];
    const float* ln1_b      = (const float*)d_in[2];
    const float* qkv_w      = (const float*)d_in[3];
    const float* qkv_b      = (const float*)d_in[4];
    const float* bias_table = (const float*)d_in[5];
    const float* proj_w     = (const float*)d_in[6];
    const float* proj_b     = (const float*)d_in[7];
    const float* ln2_g      = (const float*)d_in[8];
    const float* ln2_b      = (const float*)d_in[9];
    const float* fc1_w      = (const float*)d_in[10];
    const float* fc1_b      = (const float*)d_in[11];
    const float* fc2_w      = (const float*)d_in[12];
    const float* fc2_b      = (const float*)d_in[13];
    const float* fc3_w      = (const float*)d_in[14];
    const float* fc3_b      = (const float*)d_in[15];
    float* out = (float*)d_out;

    float *perm, *qkv, *obuf, *ybuf, *zt, *gbuf, *f1T, *f2T, *f3T;
    cudaGetSymbolAddress((void**)&perm, d_perm);
    cudaGetSymbolAddress((void**)&qkv,  d_qkv);
    cudaGetSymbolAddress((void**)&obuf, d_obuf);
    cudaGetSymbolAddress((void**)&ybuf, d_ybuf);
    cudaGetSymbolAddress((void**)&zt,   d_zt);
    cudaGetSymbolAddress((void**)&gbuf, d_gbuf);
    cudaGetSymbolAddress((void**)&f1T,  d_f1T);
    cudaGetSymbolAddress((void**)&f2T,  d_f2T);
    cudaGetSymbolAddress((void**)&f3T,  d_f3T);

    // 1) LN1 + window-partition permute
    ln1_kernel<<<NTOK / 256, 256>>>(x, ln1_g, ln1_b, perm);
    // (independent) transpose FFN weights
    transpose_w<<<(CH * DF + 255) / 256, 256>>>(fc1_w, fc2_w, fc3_w, f1T, f2T, f3T);

    // 2) QKV GEMM: (131072,192) @ (192,576)
    gemm_kernel<0, false><<<dim3(576 / 64, NTOK / 128), 256>>>(
        perm, qkv_w, nullptr, qkv_b, nullptr, nullptr, qkv, NTOK, 3 * CH, CH);

    // 3) window attention
    attn_kernel<<<dim3(NWIN, NHEAD), 64>>>(qkv, bias_table, obuf);

    // 4) proj GEMM + residual(w): (131072,192) @ (192,192)
    gemm_kernel<1, false><<<dim3(192 / 64, NTOK / 128), 256>>>(
        obuf, proj_w, nullptr, proj_b, nullptr, perm, ybuf, NTOK, CH, CH);

    // 5) LN2 + window_reverse -> token-major z
    ln2_kernel<<<NTOK / 8, 256>>>(ybuf, ln2_g, ln2_b, zt);

    // 6) gated FFN dual GEMM: sigmoid(z@fc1^T+b1) * (z@fc2^T+b2)
    gemm_kernel<2, false><<<dim3(DF / 64, NTOK / 128), 256>>>(
        zt, f1T, f2T, fc1_b, fc2_b, nullptr, gbuf, NTOK, DF, CH);

    // 7) FFN out GEMM + residual(z), scatter to (B,C,H,W)
    gemm_kernel<3, true><<<dim3(192 / 64, NTOK / 128), 256>>>(
        gbuf, f3T, nullptr, fc3_b, nullptr, zt, out, NTOK, CH, DF);
}

// round 4
// speedup vs baseline: 3.3383x; 3.3383x over previous
#include <cuda_runtime.h>
#include <cstdint>

// ---------------------------------------------------------------------------
// Problem constants (B=2, C=192, H=W=256, WS=8, NH=6, hd=32, DF=768)
// ---------------------------------------------------------------------------
#define CH    192
#define NTOK  131072
#define DF    768
#define NWIN  2048
#define WN    64

// ---------------------------------------------------------------------------
// Scratch (static device allocations)
// ---------------------------------------------------------------------------
__device__ float d_perm [NTOK * CH];
__device__ float d_qkv  [NTOK * 3 * CH];
__device__ float d_obuf [NTOK * CH];
__device__ float d_ybuf [NTOK * CH];
__device__ float d_zt   [NTOK * CH];
__device__ float d_gbuf [NTOK * DF];
__device__ float d_qkvT [576 * 192];
__device__ float d_projT[192 * 192];
__device__ float d_wI   [1536 * 192];   // interleaved fc1/fc2

// ---------------------------------------------------------------------------
// mma.sync / cp.async helpers (portable PTX, no arch-a features)
// ---------------------------------------------------------------------------
__device__ __forceinline__ uint32_t cvt_tf32(float x) {
    uint32_t r;
    asm("cvt.rna.tf32.f32 %0, %1;" : "=r"(r) : "f"(x));
    return r;
}
__device__ __forceinline__ void mma_tf32(float* d, const uint32_t* a, const uint32_t* b) {
    asm volatile(
        "mma.sync.aligned.m16n8k8.row.col.f32.tf32.tf32.f32 "
        "{%0,%1,%2,%3},{%4,%5,%6,%7},{%8,%9},{%0,%1,%2,%3};"
        : "+f"(d[0]), "+f"(d[1]), "+f"(d[2]), "+f"(d[3])
        : "r"(a[0]), "r"(a[1]), "r"(a[2]), "r"(a[3]), "r"(b[0]), "r"(b[1]));
}
__device__ __forceinline__ void cp_async16(void* dst, const void* src) {
    uint32_t d = (uint32_t)__cvta_generic_to_shared(dst);
    asm volatile("cp.async.cg.shared.global [%0], [%1], 16;" :: "r"(d), "l"(src));
}
__device__ __forceinline__ void cp_commit() { asm volatile("cp.async.commit_group;"); }
template<int N>
__device__ __forceinline__ void cp_wait() { asm volatile("cp.async.wait_group %0;" :: "n"(N)); }

// ---------------------------------------------------------------------------
// Kernel 1: LN1 over channels + channel-layout window partition (verified R0)
// ---------------------------------------------------------------------------
__global__ void ln1_kernel(const float* __restrict__ x,
                           const float* __restrict__ g,
                           const float* __restrict__ b,
                           float* __restrict__ perm)
{
    int p = blockIdx.x * blockDim.x + threadIdx.x;
    int w  = p & 255;
    int h  = (p >> 8) & 255;
    int bb = p >> 16;
    const float* xp = x + (size_t)bb * CH * 65536 + h * 256 + w;

    float sum = 0.f, sq = 0.f;
    #pragma unroll 4
    for (int c = 0; c < CH; c++) {
        float v = xp[(size_t)c * 65536];
        sum += v; sq += v * v;
    }
    float mean = sum * (1.f / CH);
    float var  = sq * (1.f / CH) - mean * mean;
    float inv  = rsqrtf(fmaxf(var, 0.f) + 1e-5f);

    int h1 = h >> 3, h2 = h & 7;
    #pragma unroll 4
    for (int c = 0; c < CH; c++) {
        float v = (xp[(size_t)c * 65536] - mean) * inv * g[c] + b[c];
        int c1 = c >> 3, c2 = c & 7;
        size_t P = (((((size_t)bb * 24 + c1) * 32 + h1) * 8 + c2) * 8 + h2) * 256 + w;
        perm[P] = v;
    }
}

// ---------------------------------------------------------------------------
// Kernel 2: weight prep — transpose qkv_w/proj_w, interleave fc1/fc2 rows
// ---------------------------------------------------------------------------
__global__ void prep_w(const float* __restrict__ qw, const float* __restrict__ pw,
                       const float* __restrict__ f1, const float* __restrict__ f2,
                       float* __restrict__ qT, float* __restrict__ pT,
                       float* __restrict__ wI)
{
    int i = blockIdx.x * blockDim.x + threadIdx.x;
    if (i < 192 * 576) { int k = i / 576, n = i % 576; qT[n * 192 + k] = qw[i]; }
    if (i < 192 * 192) { int k = i / 192, n = i % 192; pT[n * 192 + k] = pw[i]; }
    if (i < 768 * 192) {
        int j = i / 192, k = i % 192;
        wI[(size_t)(2 * j)     * 192 + k] = f1[i];
        wI[(size_t)(2 * j + 1) * 192 + k] = f2[i];
    }
}

// ---------------------------------------------------------------------------
// tf32 mma.sync GEMM: C[M,N] = A[M,K] @ Bw[N,K]^T
// block tile 128x64, 4 warps (2x2), warp tile 64x32 (4x4 of m16n8k8).
// BK=16, cp.async double-buffered, smem rows padded to 20 floats (bank-clean).
// EPI: 0 = +bias                     -> out[M,N]       (QKV)
//      1 = +bias + resid[m*N+n]      -> out[M,N]       (proj + residual)
//      2 = gate pairs: sigmoid(c0+b1)*(c1+b2) -> out[M,768]  (gated FFN, wI)
//      3 = +bias + resid[m*192+n]    -> scatter (B,C,H,W)
// ---------------------------------------------------------------------------
template<int EPI>
__global__ __launch_bounds__(128)
void mma_gemm(const float* __restrict__ A,  const float* __restrict__ Bw,
              const float* __restrict__ bias1, const float* __restrict__ bias2,
              const float* __restrict__ resid, float* __restrict__ out,
              int N, int K)
{
    __shared__ float As[2][128][20];
    __shared__ float Bs[2][64][20];

    const int tid  = threadIdx.x;
    const int warp = tid >> 5, lane = tid & 31;
    const int g = lane >> 2, cq = lane & 3;
    const int wm = warp >> 1, wn = warp & 1;
    const int M0 = blockIdx.y * 128, N0 = blockIdx.x * 64;

    float acc[4][4][4] = {};

    const int NC = K >> 4;

    // prefetch stage 0
    {
        const int k0 = 0;
        #pragma unroll
        for (int it = 0; it < 4; it++) {
            int f = tid + it * 128, row = f >> 2, vec = f & 3;
            cp_async16(&As[0][row][vec * 4], A + (size_t)(M0 + row) * K + k0 + vec * 4);
        }
        #pragma unroll
        for (int it = 0; it < 2; it++) {
            int f = tid + it * 128, row = f >> 2, vec = f & 3;
            cp_async16(&Bs[0][row][vec * 4], Bw + (size_t)(N0 + row) * K + k0 + vec * 4);
        }
    }
    cp_commit();

    for (int c = 0; c < NC; c++) {
        if (c + 1 < NC) {
            const int s = (c + 1) & 1, k0 = (c + 1) << 4;
            #pragma unroll
            for (int it = 0; it < 4; it++) {
                int f = tid + it * 128, row = f >> 2, vec = f & 3;
                cp_async16(&As[s][row][vec * 4], A + (size_t)(M0 + row) * K + k0 + vec * 4);
            }
            #pragma unroll
            for (int it = 0; it < 2; it++) {
                int f = tid + it * 128, row = f >> 2, vec = f & 3;
                cp_async16(&Bs[s][row][vec * 4], Bw + (size_t)(N0 + row) * K + k0 + vec * 4);
            }
        }
        cp_commit();
        cp_wait<1>();          // stage c is complete
        __syncthreads();

        const int s = c & 1;
        #pragma unroll
        for (int ks = 0; ks < 2; ks++) {
            uint32_t af[4][4], bf[4][2];
            #pragma unroll
            for (int mi = 0; mi < 4; mi++) {
                int r0 = wm * 64 + mi * 16 + g;
                af[mi][0] = cvt_tf32(As[s][r0    ][ks * 8 + cq    ]);
                af[mi][1] = cvt_tf32(As[s][r0 + 8][ks * 8 + cq    ]);
                af[mi][2] = cvt_tf32(As[s][r0    ][ks * 8 + cq + 4]);
                af[mi][3] = cvt_tf32(As[s][r0 + 8][ks * 8 + cq + 4]);
            }
            #pragma unroll
            for (int ni = 0; ni < 4; ni++) {
                int n0 = wn * 32 + ni * 8 + g;
                bf[ni][0] = cvt_tf32(Bs[s][n0][ks * 8 + cq    ]);
                bf[ni][1] = cvt_tf32(Bs[s][n0][ks * 8 + cq + 4]);
            }
            #pragma unroll
            for (int mi = 0; mi < 4; mi++)
                #pragma unroll
                for (int ni = 0; ni < 4; ni++)
                    mma_tf32(acc[mi][ni], af[mi], bf[ni]);
        }
        __syncthreads();
    }

    // ---- epilogue ----
    #pragma unroll
    for (int mi = 0; mi < 4; mi++) {
        #pragma unroll
        for (int ni = 0; ni < 4; ni++) {
            float* a4 = acc[mi][ni];
            const int m0 = M0 + wm * 64 + mi * 16 + g;
            const int m1 = m0 + 8;
            const int n0 = N0 + wn * 32 + ni * 8 + 2 * cq;

            if (EPI == 0) {
                float b0 = bias1[n0], b1 = bias1[n0 + 1];
                *(float2*)&out[(size_t)m0 * N + n0] = make_float2(a4[0] + b0, a4[1] + b1);
                *(float2*)&out[(size_t)m1 * N + n0] = make_float2(a4[2] + b0, a4[3] + b1);
            } else if (EPI == 1) {
                float b0 = bias1[n0], b1 = bias1[n0 + 1];
                float2 r0 = *(const float2*)&resid[(size_t)m0 * N + n0];
                float2 r1 = *(const float2*)&resid[(size_t)m1 * N + n0];
                *(float2*)&out[(size_t)m0 * N + n0] =
                    make_float2(a4[0] + b0 + r0.x, a4[1] + b1 + r0.y);
                *(float2*)&out[(size_t)m1 * N + n0] =
                    make_float2(a4[2] + b0 + r1.x, a4[3] + b1 + r1.y);
            } else if (EPI == 2) {
                // pair index: columns (2p, 2p+1) of interleaved weight = gate pair p
                int p = ((N0 + wn * 32 + ni * 8) >> 1) + cq;
                float b1 = bias1[p], b2 = bias2[p];
                float h1a = 1.f / (1.f + __expf(-(a4[0] + b1)));
                float h1b = 1.f / (1.f + __expf(-(a4[2] + b1)));
                out[(size_t)m0 * DF + p] = h1a * (a4[1] + b2);
                out[(size_t)m1 * DF + p] = h1b * (a4[3] + b2);
            } else { // EPI == 3: +bias +resid, scatter to (B,C,H,W)
                float b0 = bias1[n0], b1 = bias1[n0 + 1];
                float2 r0 = *(const float2*)&resid[(size_t)m0 * CH + n0];
                float2 r1 = *(const float2*)&resid[(size_t)m1 * CH + n0];
                int bb = m0 >> 16;
                int hw = m0 & 65535;
                size_t c0 = ((size_t)(bb * CH + n0)     << 16);
                size_t c1 = ((size_t)(bb * CH + n0 + 1) << 16);
                out[c0 + hw]     = a4[0] + b0 + r0.x;
                out[c1 + hw]     = a4[1] + b1 + r0.y;
                out[c0 + hw + 8] = a4[2] + b0 + r1.x;
                out[c1 + hw + 8] = a4[3] + b1 + r1.y;
            }
        }
    }
}

// ---------------------------------------------------------------------------
// Kernel 3: window attention, block = window (384 thr: 6 heads x 64 rows),
// online softmax (no local-memory score array).
// ---------------------------------------------------------------------------
__global__ __launch_bounds__(384)
void attn_kernel(const float* __restrict__ qkv,
                 const float* __restrict__ bias_table,
                 float* __restrict__ obuf)
{
    extern __shared__ float sm[];
    float* ks  = sm;                 // [64][192]
    float* vs  = sm + 64 * 192;      // [64][192]
    float* bsm = vs + 64 * 192;      // [6][225]

    const int bw  = blockIdx.x;
    const int tid = threadIdx.x;
    const int r   = tid & 63;
    const int h   = tid >> 6;
    const float* base = qkv + (size_t)bw * WN * (3 * CH);

    #pragma unroll
    for (int it = 0; it < 8; it++) {
        int f = tid + it * 384;           // 0..3071
        int row = f / 48, j = (f % 48) * 4;
        *(float4*)&ks[row * 192 + j] = *(const float4*)(base + (size_t)row * 576 + 192 + j);
        *(float4*)&vs[row * 192 + j] = *(const float4*)(base + (size_t)row * 576 + 384 + j);
    }
    for (int i = tid; i < 6 * 225; i += 384) {
        int hh = i / 225, e = i % 225;
        bsm[i] = bias_table[e * 6 + hh];
    }

    const float scale = 0.17677669529663687f; // 32^-0.5
    float q[32];
    const float* qrow = base + (size_t)r * 576 + h * 32;
    #pragma unroll
    for (int d = 0; d < 32; d++) q[d] = qrow[d] * scale;
    __syncthreads();

    const int it7 = (r >> 3) + 7, jt7 = (r & 7) + 7;
    const float* kh = ks + h * 32;
    const float* vh = vs + h * 32;
    const float* bh = bsm + h * 225;

    float mx = -1e30f, sum = 0.f;
    float o[32];
    #pragma unroll
    for (int d = 0; d < 32; d++) o[d] = 0.f;

    #pragma unroll 2
    for (int m = 0; m < WN; m++) {
        const float* km = kh + m * 192;
        float a = 0.f;
        #pragma unroll
        for (int d = 0; d < 32; d++) a += q[d] * km[d];
        a += bh[(it7 - (m >> 3)) * 15 + (jt7 - (m & 7))];
        float nm = fmaxf(mx, a);
        if (nm > mx) {
            float f = __expf(mx - nm);
            sum *= f;
            #pragma unroll
            for (int d = 0; d < 32; d++) o[d] *= f;
            mx = nm;
        }
        float p = __expf(a - mx);
        sum += p;
        const float* vm = vh + m * 192;
        #pragma unroll
        for (int d = 0; d < 32; d++) o[d] += p * vm[d];
    }
    float inv = 1.f / sum;
    float* orow = obuf + ((size_t)bw * WN + r) * CH + h * 32;
    #pragma unroll
    for (int d = 0; d < 32; d++) orow[d] = o[d] * inv;
}

// ---------------------------------------------------------------------------
// Kernel 4: LN2 over 192-rows of y (window layout) + window_reverse (verified R0)
// ---------------------------------------------------------------------------
__global__ __launch_bounds__(256)
void ln2_kernel(const float* __restrict__ y,
                const float* __restrict__ g,
                const float* __restrict__ b,
                float* __restrict__ zt)
{
    int tid  = threadIdx.x;
    int lane = tid & 31, wid = tid >> 5;
    int row  = blockIdx.x * 8 + wid;
    const float* yr = y + (size_t)row * CH;

    float v[6];
    float sum = 0.f, sq = 0.f;
    #pragma unroll
    for (int k = 0; k < 6; k++) {
        v[k] = yr[lane + k * 32];
        sum += v[k]; sq += v[k] * v[k];
    }
    #pragma unroll
    for (int o = 16; o > 0; o >>= 1) {
        sum += __shfl_xor_sync(0xffffffffu, sum, o);
        sq  += __shfl_xor_sync(0xffffffffu, sq,  o);
    }
    float mean = sum * (1.f / CH);
    float var  = sq * (1.f / CH) - mean * mean;
    float inv  = rsqrtf(fmaxf(var, 0.f) + 1e-5f);

    int d4 = row & 7, d3 = (row >> 3) & 7, d2 = (row >> 6) & 31,
        d1 = (row >> 11) & 31, bb = row >> 16;
    int h = d1 * 8 + d3, w = d2 * 8 + d4;
    int t = ((bb * 256 + h) << 8) + w;
    float* zr = zt + (size_t)t * CH;
    #pragma unroll
    for (int k = 0; k < 6; k++) {
        int c = lane + k * 32;
        zr[c] = (v[k] - mean) * inv * g[c] + b[c];
    }
}

// ---------------------------------------------------------------------------
// kernel_launch
// ---------------------------------------------------------------------------
extern "C" void kernel_launch(void* const* d_in, const int* in_sizes, int n_in,
                              void* d_out, int out_size)
{
    const float* x          = (const float*)d_in[0];
    const float* ln1_g      = (const float*)d_in[1];
    const float* ln1_b      = (const float*)d_in[2];
    const float* qkv_w      = (const float*)d_in[3];
    const float* qkv_b      = (const float*)d_in[4];
    const float* bias_table = (const float*)d_in[5];
    const float* proj_w     = (const float*)d_in[6];
    const float* proj_b     = (const float*)d_in[7];
    const float* ln2_g      = (const float*)d_in[8];
    const float* ln2_b      = (const float*)d_in[9];
    const float* fc1_w      = (const float*)d_in[10];
    const float* fc1_b      = (const float*)d_in[11];
    const float* fc2_w      = (const float*)d_in[12];
    const float* fc2_b      = (const float*)d_in[13];
    const float* fc3_w      = (const float*)d_in[14];
    const float* fc3_b      = (const float*)d_in[15];
    float* out = (float*)d_out;

    float *perm, *qkv, *obuf, *ybuf, *zt, *gbuf, *qT, *pT, *wI;
    cudaGetSymbolAddress((void**)&perm, d_perm);
    cudaGetSymbolAddress((void**)&qkv,  d_qkv);
    cudaGetSymbolAddress((void**)&obuf, d_obuf);
    cudaGetSymbolAddress((void**)&ybuf, d_ybuf);
    cudaGetSymbolAddress((void**)&zt,   d_zt);
    cudaGetSymbolAddress((void**)&gbuf, d_gbuf);
    cudaGetSymbolAddress((void**)&qT,   d_qkvT);
    cudaGetSymbolAddress((void**)&pT,   d_projT);
    cudaGetSymbolAddress((void**)&wI,   d_wI);

    const int SMEM_ATTN = (64 * 192 * 2 + 6 * 225) * 4;
    cudaFuncSetAttribute(attn_kernel, cudaFuncAttributeMaxDynamicSharedMemorySize, SMEM_ATTN);

    // 1) LN1 + window-partition permute; weight prep
    ln1_kernel<<<NTOK / 256, 256>>>(x, ln1_g, ln1_b, perm);
    prep_w<<<(768 * 192 + 255) / 256, 256>>>(qkv_w, proj_w, fc1_w, fc2_w, qT, pT, wI);

    // 2) QKV GEMM: (131072,192) @ (576,192)^T
    mma_gemm<0><<<dim3(9, 1024), 128>>>(perm, qT, qkv_b, nullptr, nullptr, qkv, 576, 192);

    // 3) window attention
    attn_kernel<<<NWIN, 384, SMEM_ATTN>>>(qkv, bias_table, obuf);

    // 4) proj GEMM + residual
    mma_gemm<1><<<dim3(3, 1024), 128>>>(obuf, pT, proj_b, nullptr, perm, ybuf, 192, 192);

    // 5) LN2 + window_reverse -> token-major z
    ln2_kernel<<<NTOK / 8, 256>>>(ybuf, ln2_g, ln2_b, zt);

    // 6) gated FFN (interleaved dual): N=1536 tiles, out = sigmoid(h1)*h2 -> [M,768]
    mma_gemm<2><<<dim3(24, 1024), 128>>>(zt, wI, fc1_b, fc2_b, nullptr, gbuf, 1536, 192);

    // 7) FFN out GEMM + residual(z), scatter to (B,C,H,W)
    mma_gemm<3><<<dim3(3, 1024), 128>>>(gbuf, fc3_w, fc3_b, nullptr, zt, out, 192, 768);
}